// round 2
// baseline (speedup 1.0000x reference)
#include <cuda_runtime.h>
#include <cuda_fp16.h>
#include <math.h>
#include <stdint.h>

#define T 2048
#define D 2048
#define E 8
#define F 1408

// ---------------- scratch (device globals; no allocation allowed) ----------
__device__ __align__(16) __half g_Wg[(size_t)E * D * F];   // 46 MB
__device__ __align__(16) __half g_Wu[(size_t)E * D * F];   // 46 MB
__device__ __align__(16) __half g_Wd[(size_t)E * F * D];   // 46 MB
__device__ __align__(16) __half g_X [(size_t)E * T * D];   // 67 MB (gathered activations)
__device__ __align__(16) __half g_H [(size_t)E * T * F];   // 46 MB (silu(g)*u)
__device__ int   g_cnt[E];
__device__ int   g_tok[E * T];
__device__ float g_wt [E * T];

// ---------------- tiny helpers ---------------------------------------------
__global__ void zero_cnt_kernel() {
    if (threadIdx.x < E) g_cnt[threadIdx.x] = 0;
}

// fp32 -> fp16 bulk convert into one of the three weight scratch arrays
__global__ void convert_kernel(const float4* __restrict__ src, int which, int n4) {
    __half2* dst = (which == 0) ? (__half2*)g_Wg
                 : (which == 1) ? (__half2*)g_Wu
                                : (__half2*)g_Wd;
    for (int i = blockIdx.x * blockDim.x + threadIdx.x; i < n4;
         i += gridDim.x * blockDim.x) {
        float4 v = src[i];
        dst[2 * i + 0] = __floats2half2_rn(v.x, v.y);
        dst[2 * i + 1] = __floats2half2_rn(v.z, v.w);
    }
}

// ---------------- router: logits -> softmax -> top2 -> expert lists --------
__global__ void router_kernel(const float* __restrict__ x,
                              const float* __restrict__ gw) {
    int t = blockIdx.x;
    const float* xr = x + (size_t)t * D;
    float acc[E];
#pragma unroll
    for (int e = 0; e < E; e++) acc[e] = 0.f;
    for (int d = threadIdx.x; d < D; d += blockDim.x) {
        float xv = xr[d];
#pragma unroll
        for (int e = 0; e < E; e++) acc[e] += xv * gw[e * D + d];
    }
    __shared__ float s[E][256];
#pragma unroll
    for (int e = 0; e < E; e++) s[e][threadIdx.x] = acc[e];
    __syncthreads();
    for (int st = 128; st > 0; st >>= 1) {
        if (threadIdx.x < st) {
#pragma unroll
            for (int e = 0; e < E; e++)
                s[e][threadIdx.x] += s[e][threadIdx.x + st];
        }
        __syncthreads();
    }
    if (threadIdx.x == 0) {
        float l[E], m = -1e30f;
#pragma unroll
        for (int e = 0; e < E; e++) { l[e] = s[e][0]; m = fmaxf(m, l[e]); }
        float p[E], sum = 0.f;
#pragma unroll
        for (int e = 0; e < E; e++) { p[e] = expf(l[e] - m); sum += p[e]; }
        float inv = 1.f / sum;
#pragma unroll
        for (int e = 0; e < E; e++) p[e] *= inv;
        // top-2 with jax tie-break (lowest index wins on ties -> strict >)
        int i1 = 0;
#pragma unroll
        for (int e = 1; e < E; e++) if (p[e] > p[i1]) i1 = e;
        int i2 = -1;
#pragma unroll
        for (int e = 0; e < E; e++)
            if (e != i1 && (i2 < 0 || p[e] > p[i2])) i2 = e;
        int r1 = atomicAdd(&g_cnt[i1], 1);
        g_tok[i1 * T + r1] = t;  g_wt[i1 * T + r1] = p[i1];
        int r2 = atomicAdd(&g_cnt[i2], 1);
        g_tok[i2 * T + r2] = t;  g_wt[i2 * T + r2] = p[i2];
    }
}

// ---------------- gather selected rows to fp16 per-expert buffers ----------
__global__ void gather_kernel(const float* __restrict__ x) {
    int e = blockIdx.y;
    int r = blockIdx.x;
    if (r >= g_cnt[e]) return;
    int t = g_tok[e * T + r];
    const float4* src = (const float4*)(x + (size_t)t * D);
    __half2* dst = (__half2*)(g_X + ((size_t)e * T + r) * D);
    for (int i = threadIdx.x; i < D / 4; i += blockDim.x) {
        float4 v = src[i];
        dst[2 * i + 0] = __floats2half2_rn(v.x, v.y);
        dst[2 * i + 1] = __floats2half2_rn(v.z, v.w);
    }
}

// ---------------- mma.sync wrapper -----------------------------------------
__device__ __forceinline__ void mma16816(float* c, const unsigned* a,
                                         const unsigned* b) {
    asm volatile(
        "mma.sync.aligned.m16n8k16.row.col.f32.f16.f16.f32 "
        "{%0,%1,%2,%3}, {%4,%5,%6,%7}, {%8,%9}, {%0,%1,%2,%3};\n"
        : "+f"(c[0]), "+f"(c[1]), "+f"(c[2]), "+f"(c[3])
        : "r"(a[0]), "r"(a[1]), "r"(a[2]), "r"(a[3]), "r"(b[0]), "r"(b[1]));
}

#define BM 64
#define BN 64
#define BK 32
#define SPAD 8   // smem stride pad: stride 40 halfs -> conflict-free frag LDS

// ---------------- GEMM1: H = silu(X @ Wg) * (X @ Wu), per expert -----------
__global__ __launch_bounds__(128) void gemm1_kernel() {
    int e = blockIdx.z;
    int cnt = g_cnt[e];
    int m0 = blockIdx.y * BM;
    if (m0 >= cnt) return;
    int n0 = blockIdx.x * BN;

    __shared__ __half As[BM][BK + SPAD];
    __shared__ __half Bg[BN][BK + SPAD];
    __shared__ __half Bu[BN][BK + SPAD];

    const __half* A  = g_X  + ((size_t)e * T + m0) * D;
    const __half* WG = g_Wg + (size_t)e * D * F;
    const __half* WU = g_Wu + (size_t)e * D * F;

    int tid  = threadIdx.x;
    int warp = tid >> 5, lane = tid & 31;
    int wm = (warp >> 1) * 32;
    int wn = (warp & 1) * 32;
    int grp = lane >> 2, tig = lane & 3;

    float accG[2][4][4], accU[2][4][4];
#pragma unroll
    for (int mi = 0; mi < 2; mi++)
#pragma unroll
        for (int ni = 0; ni < 4; ni++)
#pragma unroll
            for (int q = 0; q < 4; q++) { accG[mi][ni][q] = 0.f; accU[mi][ni][q] = 0.f; }

    for (int k0 = 0; k0 < D; k0 += BK) {
        // A tile: 64 x 32 halfs, uint4 per thread
        {
            int row  = tid >> 2;
            int colq = (tid & 3) * 8;
#pragma unroll
            for (int p = 0; p < 2; p++) {
                int r = row + p * 32;
                uint4 v = *(const uint4*)(A + (size_t)r * D + k0 + colq);
                *(uint4*)(&As[r][colq]) = v;
            }
        }
        // B tiles (gate & up): 32(k) x 64(n) -> transposed [n][k]
        {
            int k  = tid >> 3;
            int nq = (tid & 7) * 8;
#pragma unroll
            for (int p = 0; p < 2; p++) {
                int kk = k + p * 16;
                uint4 vg = *(const uint4*)(WG + (size_t)(k0 + kk) * F + n0 + nq);
                uint4 vu = *(const uint4*)(WU + (size_t)(k0 + kk) * F + n0 + nq);
                __half hg[8]; *(uint4*)hg = vg;
                __half hu[8]; *(uint4*)hu = vu;
#pragma unroll
                for (int j = 0; j < 8; j++) {
                    Bg[nq + j][kk] = hg[j];
                    Bu[nq + j][kk] = hu[j];
                }
            }
        }
        __syncthreads();
#pragma unroll
        for (int kk = 0; kk < BK; kk += 16) {
            unsigned a[2][4], bg[4][2], bu[4][2];
            int col = kk + tig * 2;
#pragma unroll
            for (int mi = 0; mi < 2; mi++) {
                int row = wm + mi * 16 + grp;
                a[mi][0] = *(const unsigned*)&As[row][col];
                a[mi][1] = *(const unsigned*)&As[row + 8][col];
                a[mi][2] = *(const unsigned*)&As[row][col + 8];
                a[mi][3] = *(const unsigned*)&As[row + 8][col + 8];
            }
#pragma unroll
            for (int ni = 0; ni < 4; ni++) {
                int n = wn + ni * 8 + grp;
                bg[ni][0] = *(const unsigned*)&Bg[n][col];
                bg[ni][1] = *(const unsigned*)&Bg[n][col + 8];
                bu[ni][0] = *(const unsigned*)&Bu[n][col];
                bu[ni][1] = *(const unsigned*)&Bu[n][col + 8];
            }
#pragma unroll
            for (int mi = 0; mi < 2; mi++)
#pragma unroll
                for (int ni = 0; ni < 4; ni++) {
                    mma16816(accG[mi][ni], a[mi], bg[ni]);
                    mma16816(accU[mi][ni], a[mi], bu[ni]);
                }
        }
        __syncthreads();
    }

    // epilogue: silu(g)*u -> fp16 H
    __half* Hp = g_H + (size_t)e * T * F;
#pragma unroll
    for (int mi = 0; mi < 2; mi++) {
#pragma unroll
        for (int h = 0; h < 2; h++) {
            int grow = m0 + wm + mi * 16 + grp + h * 8;
            if (grow >= cnt) continue;
            __half2* hrow = (__half2*)(Hp + (size_t)grow * F);
#pragma unroll
            for (int ni = 0; ni < 4; ni++) {
                int col = n0 + wn + ni * 8 + tig * 2;
                float g0 = accG[mi][ni][h * 2 + 0], u0 = accU[mi][ni][h * 2 + 0];
                float g1 = accG[mi][ni][h * 2 + 1], u1 = accU[mi][ni][h * 2 + 1];
                float h0 = (g0 / (1.f + __expf(-g0))) * u0;
                float h1 = (g1 / (1.f + __expf(-g1))) * u1;
                hrow[col >> 1] = __floats2half2_rn(h0, h1);
            }
        }
    }
}

// ---------------- GEMM2: out += wt * (H @ Wd), per expert ------------------
__global__ __launch_bounds__(128) void gemm2_kernel(float* __restrict__ out) {
    int e = blockIdx.z;
    int cnt = g_cnt[e];
    int m0 = blockIdx.y * BM;
    if (m0 >= cnt) return;
    int n0 = blockIdx.x * BN;

    __shared__ __half As[BM][BK + SPAD];
    __shared__ __half Bs[BN][BK + SPAD];

    const __half* A  = g_H  + ((size_t)e * T + m0) * F;
    const __half* WD = g_Wd + (size_t)e * F * D;

    int tid  = threadIdx.x;
    int warp = tid >> 5, lane = tid & 31;
    int wm = (warp >> 1) * 32;
    int wn = (warp & 1) * 32;
    int grp = lane >> 2, tig = lane & 3;

    float acc[2][4][4];
#pragma unroll
    for (int mi = 0; mi < 2; mi++)
#pragma unroll
        for (int ni = 0; ni < 4; ni++)
#pragma unroll
            for (int q = 0; q < 4; q++) acc[mi][ni][q] = 0.f;

    for (int k0 = 0; k0 < F; k0 += BK) {
        {
            int row  = tid >> 2;
            int colq = (tid & 3) * 8;
#pragma unroll
            for (int p = 0; p < 2; p++) {
                int r = row + p * 32;
                uint4 v = *(const uint4*)(A + (size_t)r * F + k0 + colq);
                *(uint4*)(&As[r][colq]) = v;
            }
        }
        {
            int k  = tid >> 3;
            int nq = (tid & 7) * 8;
#pragma unroll
            for (int p = 0; p < 2; p++) {
                int kk = k + p * 16;
                uint4 vb = *(const uint4*)(WD + (size_t)(k0 + kk) * D + n0 + nq);
                __half hb[8]; *(uint4*)hb = vb;
#pragma unroll
                for (int j = 0; j < 8; j++) Bs[nq + j][kk] = hb[j];
            }
        }
        __syncthreads();
#pragma unroll
        for (int kk = 0; kk < BK; kk += 16) {
            unsigned a[2][4], b[4][2];
            int col = kk + tig * 2;
#pragma unroll
            for (int mi = 0; mi < 2; mi++) {
                int row = wm + mi * 16 + grp;
                a[mi][0] = *(const unsigned*)&As[row][col];
                a[mi][1] = *(const unsigned*)&As[row + 8][col];
                a[mi][2] = *(const unsigned*)&As[row][col + 8];
                a[mi][3] = *(const unsigned*)&As[row + 8][col + 8];
            }
#pragma unroll
            for (int ni = 0; ni < 4; ni++) {
                int n = wn + ni * 8 + grp;
                b[ni][0] = *(const unsigned*)&Bs[n][col];
                b[ni][1] = *(const unsigned*)&Bs[n][col + 8];
            }
#pragma unroll
            for (int mi = 0; mi < 2; mi++)
#pragma unroll
                for (int ni = 0; ni < 4; ni++)
                    mma16816(acc[mi][ni], a[mi], b[ni]);
        }
        __syncthreads();
    }

    // epilogue: weighted atomic combine
    int base = e * T;
#pragma unroll
    for (int mi = 0; mi < 2; mi++) {
#pragma unroll
        for (int h = 0; h < 2; h++) {
            int grow = m0 + wm + mi * 16 + grp + h * 8;
            if (grow >= cnt) continue;
            int   tokv = g_tok[base + grow];
            float wv   = g_wt [base + grow];
            float* orow = out + (size_t)tokv * D;
#pragma unroll
            for (int ni = 0; ni < 4; ni++) {
                int col = n0 + wn + ni * 8 + tig * 2;
                atomicAdd(&orow[col],     acc[mi][ni][h * 2 + 0] * wv);
                atomicAdd(&orow[col + 1], acc[mi][ni][h * 2 + 1] * wv);
            }
        }
    }
}

// ---------------- launch ----------------------------------------------------
extern "C" void kernel_launch(void* const* d_in, const int* in_sizes, int n_in,
                              void* d_out, int out_size) {
    const float* x  = (const float*)d_in[0];
    const float* gw = (const float*)d_in[1];
    const float* wg = (const float*)d_in[2];
    const float* wu = (const float*)d_in[3];
    const float* wd = (const float*)d_in[4];
    float* out = (float*)d_out;

    cudaMemsetAsync(d_out, 0, (size_t)T * D * sizeof(float), 0);
    zero_cnt_kernel<<<1, 32>>>();

    const int n4 = (E * D * F) / 4;  // 5,767,168
    convert_kernel<<<4096, 256>>>((const float4*)wg, 0, n4);
    convert_kernel<<<4096, 256>>>((const float4*)wu, 1, n4);
    convert_kernel<<<4096, 256>>>((const float4*)wd, 2, n4);

    router_kernel<<<T, 256>>>(x, gw);
    gather_kernel<<<dim3(T, E), 128>>>(x);

    gemm1_kernel<<<dim3(F / BN, T / BM, E), 128>>>();
    gemm2_kernel<<<dim3(D / BN, T / BM, E), 128>>>(out);
}

// round 3
// speedup vs baseline: 2.5228x; 2.5228x over previous
#include <cuda_runtime.h>
#include <cuda_fp16.h>
#include <math.h>
#include <stdint.h>

#define T 2048
#define D 2048
#define E 8
#define F 1408
#define N1 (2 * F)   // interleaved gate/up N dimension = 2816

// ---------------- scratch (device globals; no allocation allowed) ----------
__device__ __align__(16) __half g_Wgu[(size_t)E * D * N1];  // 92 MB interleaved gate/up
__device__ __align__(16) __half g_Wd [(size_t)E * F * D];   // 46 MB
__device__ __align__(16) __half g_X  [(size_t)E * T * D];   // 67 MB gathered activations
__device__ __align__(16) __half g_H  [(size_t)E * T * F];   // 46 MB silu(g)*u
__device__ int   g_cnt[E];
__device__ int   g_tok[E * T];
__device__ float g_wt [E * T];

// ---------------- helpers ---------------------------------------------------
__global__ void zero_cnt_kernel() {
    if (threadIdx.x < E) g_cnt[threadIdx.x] = 0;
}

// fused gate+up convert with column interleave: dst[2f]=gate_f, dst[2f+1]=up_f
__global__ void convert_gu_kernel(const float4* __restrict__ wg,
                                  const float4* __restrict__ wu, int n4) {
    uint4* dst = (uint4*)g_Wgu;
    for (int i = blockIdx.x * blockDim.x + threadIdx.x; i < n4;
         i += gridDim.x * blockDim.x) {
        float4 g = wg[i];
        float4 u = wu[i];
        __half2 h[4];
        h[0] = __floats2half2_rn(g.x, u.x);
        h[1] = __floats2half2_rn(g.y, u.y);
        h[2] = __floats2half2_rn(g.z, u.z);
        h[3] = __floats2half2_rn(g.w, u.w);
        dst[i] = *(uint4*)h;
    }
}

__global__ void convert_d_kernel(const float4* __restrict__ src, int n4) {
    __half2* dst = (__half2*)g_Wd;
    for (int i = blockIdx.x * blockDim.x + threadIdx.x; i < n4;
         i += gridDim.x * blockDim.x) {
        float4 v = src[i];
        dst[2 * i + 0] = __floats2half2_rn(v.x, v.y);
        dst[2 * i + 1] = __floats2half2_rn(v.z, v.w);
    }
}

// ---------------- router ----------------------------------------------------
__global__ void router_kernel(const float* __restrict__ x,
                              const float* __restrict__ gw) {
    int t = blockIdx.x;
    const float* xr = x + (size_t)t * D;
    float acc[E];
#pragma unroll
    for (int e = 0; e < E; e++) acc[e] = 0.f;
    for (int d = threadIdx.x; d < D; d += blockDim.x) {
        float xv = xr[d];
#pragma unroll
        for (int e = 0; e < E; e++) acc[e] += xv * gw[e * D + d];
    }
    __shared__ float s[E][256];
#pragma unroll
    for (int e = 0; e < E; e++) s[e][threadIdx.x] = acc[e];
    __syncthreads();
    for (int st = 128; st > 0; st >>= 1) {
        if (threadIdx.x < st) {
#pragma unroll
            for (int e = 0; e < E; e++)
                s[e][threadIdx.x] += s[e][threadIdx.x + st];
        }
        __syncthreads();
    }
    if (threadIdx.x == 0) {
        float l[E], m = -1e30f;
#pragma unroll
        for (int e = 0; e < E; e++) { l[e] = s[e][0]; m = fmaxf(m, l[e]); }
        float p[E], sum = 0.f;
#pragma unroll
        for (int e = 0; e < E; e++) { p[e] = expf(l[e] - m); sum += p[e]; }
        float inv = 1.f / sum;
#pragma unroll
        for (int e = 0; e < E; e++) p[e] *= inv;
        int i1 = 0;
#pragma unroll
        for (int e = 1; e < E; e++) if (p[e] > p[i1]) i1 = e;
        int i2 = -1;
#pragma unroll
        for (int e = 0; e < E; e++)
            if (e != i1 && (i2 < 0 || p[e] > p[i2])) i2 = e;
        int r1 = atomicAdd(&g_cnt[i1], 1);
        g_tok[i1 * T + r1] = t;  g_wt[i1 * T + r1] = p[i1];
        int r2 = atomicAdd(&g_cnt[i2], 1);
        g_tok[i2 * T + r2] = t;  g_wt[i2 * T + r2] = p[i2];
    }
}

// ---------------- gather ----------------------------------------------------
__global__ void gather_kernel(const float* __restrict__ x) {
    int e = blockIdx.y;
    int r = blockIdx.x;
    if (r >= g_cnt[e]) return;
    int t = g_tok[e * T + r];
    const float4* src = (const float4*)(x + (size_t)t * D);
    __half2* dst = (__half2*)(g_X + ((size_t)e * T + r) * D);
    for (int i = threadIdx.x; i < D / 4; i += blockDim.x) {
        float4 v = src[i];
        dst[2 * i + 0] = __floats2half2_rn(v.x, v.y);
        dst[2 * i + 1] = __floats2half2_rn(v.z, v.w);
    }
}

// ---------------- PTX primitives --------------------------------------------
__device__ __forceinline__ unsigned smem_u32(const void* p) {
    return (unsigned)__cvta_generic_to_shared(p);
}
__device__ __forceinline__ void cp16(void* dst, const void* src) {
    asm volatile("cp.async.cg.shared.global [%0], [%1], 16;\n"
                 :: "r"(smem_u32(dst)), "l"(src));
}
__device__ __forceinline__ void cp_commit() {
    asm volatile("cp.async.commit_group;\n");
}
template <int N>
__device__ __forceinline__ void cp_wait() {
    asm volatile("cp.async.wait_group %0;\n" :: "n"(N));
}
__device__ __forceinline__ void ldsm_x4(unsigned& r0, unsigned& r1,
                                        unsigned& r2, unsigned& r3,
                                        const void* p) {
    asm volatile("ldmatrix.sync.aligned.m8n8.x4.shared.b16 {%0,%1,%2,%3}, [%4];\n"
                 : "=r"(r0), "=r"(r1), "=r"(r2), "=r"(r3) : "r"(smem_u32(p)));
}
__device__ __forceinline__ void ldsm_x4t(unsigned& r0, unsigned& r1,
                                         unsigned& r2, unsigned& r3,
                                         const void* p) {
    asm volatile("ldmatrix.sync.aligned.m8n8.x4.trans.shared.b16 {%0,%1,%2,%3}, [%4];\n"
                 : "=r"(r0), "=r"(r1), "=r"(r2), "=r"(r3) : "r"(smem_u32(p)));
}
__device__ __forceinline__ void mma16816(float* c, const unsigned* a,
                                         const unsigned* b) {
    asm volatile(
        "mma.sync.aligned.m16n8k16.row.col.f32.f16.f16.f32 "
        "{%0,%1,%2,%3}, {%4,%5,%6,%7}, {%8,%9}, {%0,%1,%2,%3};\n"
        : "+f"(c[0]), "+f"(c[1]), "+f"(c[2]), "+f"(c[3])
        : "r"(a[0]), "r"(a[1]), "r"(a[2]), "r"(a[3]), "r"(b[0]), "r"(b[1]));
}

// ---------------- tiled GEMM config -----------------------------------------
#define BM 128
#define BN 128
#define BK 32
#define APAD 8            // A row stride 40 halfs = 80B (conflict-free ldmatrix)
#define BPAD 8            // B row stride 136 halfs = 272B (conflict-free ldmatrix)

// Shared mainloop body as a macro so GEMM1/GEMM2 keep identical pipelines.
// As: [2][BM][BK+APAD]  (row-major m x k)
// Bs: [2][BK][BN+BPAD]  (row-major k x n)

#define GEMM_LOAD_TILE(s, Aptr, ldA, Bptr, ldB, kk0)                           \
    {                                                                          \
        _Pragma("unroll")                                                      \
        for (int c = tid; c < 512; c += 256) {                                 \
            int row = c >> 2, col8 = (c & 3) * 8;                              \
            cp16(&As[s][row][col8], Aptr + (size_t)row * (ldA) + (kk0) + col8);\
        }                                                                      \
        _Pragma("unroll")                                                      \
        for (int c = tid; c < 512; c += 256) {                                 \
            int row = c >> 4, col8 = (c & 15) * 8;                             \
            cp16(&Bs[s][row][col8],                                            \
                 Bptr + (size_t)((kk0) + row) * (ldB) + n0 + col8);            \
        }                                                                      \
        cp_commit();                                                           \
    }

#define GEMM_COMPUTE_STAGE(s)                                                  \
    {                                                                          \
        _Pragma("unroll")                                                      \
        for (int ks = 0; ks < BK; ks += 16) {                                  \
            unsigned a[4][4], b[4][2];                                         \
            int arow = (lane & 15), acol = ks + ((lane >> 4) << 3);            \
            _Pragma("unroll")                                                  \
            for (int mi = 0; mi < 4; mi++)                                     \
                ldsm_x4(a[mi][0], a[mi][1], a[mi][2], a[mi][3],                \
                        &As[s][wm + mi * 16 + arow][acol]);                    \
            int brow = ks + (lane & 15);                                       \
            _Pragma("unroll")                                                  \
            for (int nj = 0; nj < 2; nj++) {                                   \
                unsigned r0, r1, r2, r3;                                       \
                ldsm_x4t(r0, r1, r2, r3,                                       \
                         &Bs[s][brow][wn + nj * 16 + ((lane >> 4) << 3)]);     \
                b[2 * nj][0] = r0; b[2 * nj][1] = r1;                          \
                b[2 * nj + 1][0] = r2; b[2 * nj + 1][1] = r3;                  \
            }                                                                  \
            _Pragma("unroll")                                                  \
            for (int mi = 0; mi < 4; mi++)                                     \
                _Pragma("unroll")                                              \
                for (int ni = 0; ni < 4; ni++)                                 \
                    mma16816(acc[mi][ni], a[mi], b[ni]);                       \
        }                                                                      \
    }

// ---------------- GEMM1: H = silu(X @ Wgate) * (X @ Wup) --------------------
__global__ __launch_bounds__(256) void gemm1_kernel() {
    int e = blockIdx.z;
    int cnt = g_cnt[e];
    int m0 = blockIdx.y * BM;
    if (m0 >= cnt) return;
    int n0 = blockIdx.x * BN;

    __shared__ __half As[2][BM][BK + APAD];
    __shared__ __half Bs[2][BK][BN + BPAD];

    const __half* A = g_X   + ((size_t)e * T + m0) * D;
    const __half* B = g_Wgu + (size_t)e * D * N1;

    int tid = threadIdx.x;
    int warp = tid >> 5, lane = tid & 31;
    int wm = (warp >> 2) * 64;          // 2 warp rows of 64
    int wn = (warp & 3) * 32;           // 4 warp cols of 32
    int grp = lane >> 2, tig = lane & 3;

    float acc[4][4][4];
#pragma unroll
    for (int mi = 0; mi < 4; mi++)
#pragma unroll
        for (int ni = 0; ni < 4; ni++)
#pragma unroll
            for (int q = 0; q < 4; q++) acc[mi][ni][q] = 0.f;

    const int NK = D / BK;  // 64
    GEMM_LOAD_TILE(0, A, D, B, N1, 0)
    int s = 0;
    for (int kt = 0; kt < NK; kt++) {
        if (kt + 1 < NK) {
            GEMM_LOAD_TILE(s ^ 1, A, D, B, N1, (kt + 1) * BK)
            cp_wait<1>();
        } else {
            cp_wait<0>();
        }
        __syncthreads();
        GEMM_COMPUTE_STAGE(s)
        __syncthreads();
        s ^= 1;
    }

    // epilogue: (c0,c1)=(gate,up) per thread thanks to column interleave
    __half* Hp = g_H + (size_t)e * T * F;
#pragma unroll
    for (int mi = 0; mi < 4; mi++) {
#pragma unroll
        for (int h = 0; h < 2; h++) {
            int grow = m0 + wm + mi * 16 + grp + h * 8;
            if (grow >= cnt) continue;
            __half* hrow = Hp + (size_t)grow * F;
#pragma unroll
            for (int ni = 0; ni < 4; ni++) {
                int ng = n0 + wn + ni * 8;        // even, interleaved base
                int f = (ng >> 1) + tig;          // output feature index
                float g = acc[mi][ni][h * 2 + 0];
                float u = acc[mi][ni][h * 2 + 1];
                float hv = (g / (1.f + __expf(-g))) * u;
                hrow[f] = __float2half_rn(hv);
            }
        }
    }
}

// ---------------- GEMM2: out += wt * (H @ Wd) -------------------------------
__global__ __launch_bounds__(256) void gemm2_kernel(float* __restrict__ out) {
    int e = blockIdx.z;
    int cnt = g_cnt[e];
    int m0 = blockIdx.y * BM;
    if (m0 >= cnt) return;
    int n0 = blockIdx.x * BN;

    __shared__ __half As[2][BM][BK + APAD];
    __shared__ __half Bs[2][BK][BN + BPAD];

    const __half* A = g_H  + ((size_t)e * T + m0) * F;
    const __half* B = g_Wd + (size_t)e * F * D;

    int tid = threadIdx.x;
    int warp = tid >> 5, lane = tid & 31;
    int wm = (warp >> 2) * 64;
    int wn = (warp & 3) * 32;
    int grp = lane >> 2, tig = lane & 3;

    float acc[4][4][4];
#pragma unroll
    for (int mi = 0; mi < 4; mi++)
#pragma unroll
        for (int ni = 0; ni < 4; ni++)
#pragma unroll
            for (int q = 0; q < 4; q++) acc[mi][ni][q] = 0.f;

    const int NK = F / BK;  // 44
    GEMM_LOAD_TILE(0, A, F, B, D, 0)
    int s = 0;
    for (int kt = 0; kt < NK; kt++) {
        if (kt + 1 < NK) {
            GEMM_LOAD_TILE(s ^ 1, A, F, B, D, (kt + 1) * BK)
            cp_wait<1>();
        } else {
            cp_wait<0>();
        }
        __syncthreads();
        GEMM_COMPUTE_STAGE(s)
        __syncthreads();
        s ^= 1;
    }

    int base = e * T;
#pragma unroll
    for (int mi = 0; mi < 4; mi++) {
#pragma unroll
        for (int h = 0; h < 2; h++) {
            int grow = m0 + wm + mi * 16 + grp + h * 8;
            if (grow >= cnt) continue;
            int   tokv = g_tok[base + grow];
            float wv   = g_wt [base + grow];
            float* orow = out + (size_t)tokv * D;
#pragma unroll
            for (int ni = 0; ni < 4; ni++) {
                int col = n0 + wn + ni * 8 + tig * 2;
                atomicAdd(&orow[col],     acc[mi][ni][h * 2 + 0] * wv);
                atomicAdd(&orow[col + 1], acc[mi][ni][h * 2 + 1] * wv);
            }
        }
    }
}

// ---------------- launch ----------------------------------------------------
extern "C" void kernel_launch(void* const* d_in, const int* in_sizes, int n_in,
                              void* d_out, int out_size) {
    const float* x  = (const float*)d_in[0];
    const float* gw = (const float*)d_in[1];
    const float* wg = (const float*)d_in[2];
    const float* wu = (const float*)d_in[3];
    const float* wd = (const float*)d_in[4];
    float* out = (float*)d_out;

    cudaMemsetAsync(d_out, 0, (size_t)T * D * sizeof(float), 0);
    zero_cnt_kernel<<<1, 32>>>();

    const int n4 = (E * D * F) / 4;  // 5,767,168
    convert_gu_kernel<<<4096, 256>>>((const float4*)wg, (const float4*)wu, n4);
    convert_d_kernel<<<4096, 256>>>((const float4*)wd, n4);

    router_kernel<<<T, 256>>>(x, gw);
    gather_kernel<<<dim3(T, E), 128>>>(x);

    gemm1_kernel<<<dim3(N1 / BN, T / BM, E), 256>>>();
    gemm2_kernel<<<dim3(D / BN, T / BM, E), 256>>>(out);
}